// round 7
// baseline (speedup 1.0000x reference)
#include <cuda_runtime.h>
#include <cuda_bf16.h>
#include <cuda_fp16.h>
#include <stdint.h>

#define N_NODES 100000
#define N_EDGES 1600000
#define D_IN    256
#define D_OUT   128
#define N_TILES ((N_NODES + 127) / 128)   // 782

// ---------------- device scratch (no allocations allowed) ----------------
// support stored as fp16, packed half2 in u32: [N_NODES][64] u32
__device__ uint32_t g_support_h[(size_t)N_NODES * (D_OUT / 2)];   // 25.6 MB
__device__ int   g_counts[N_NODES];
__device__ int   g_rowptr[N_NODES + 1];
__device__ int   g_cursor[N_NODES];
__device__ int2  g_sorted_cv[N_EDGES];                 // (col, val-bits) sorted by row

#define SCAN_B 1024
#define NSB    ((N_NODES + SCAN_B - 1) / SCAN_B)       // 98
__device__ int   g_blocksums[NSB];

#define WSTRIDE 132

// ---------------- 1) HMMA GEMM: support = X @ W (fp16 output) ------------
#define ASTRIDE 20
#define W_U32   (128 * WSTRIDE)
#define A_U32   (128 * ASTRIDE)
#define SM_TOTAL_B ((2 * W_U32 + 4 * A_U32) * 4)   // 176128 bytes

// pack two fp32 -> bf16x2 (f0 low half, f1 high half)
__device__ __forceinline__ uint32_t pack_bf(float f0, float f1) {
    uint32_t r;
    asm("cvt.rn.bf16x2.f32 %0, %1, %2;" : "=r"(r) : "f"(f1), "f"(f0));
    return r;
}

__device__ __forceinline__ void mma16816(float* d, const uint32_t* a, const uint32_t* b) {
    asm volatile(
        "mma.sync.aligned.m16n8k16.row.col.f32.bf16.bf16.f32 "
        "{%0,%1,%2,%3}, {%4,%5,%6,%7}, {%8,%9}, {%0,%1,%2,%3};"
        : "+f"(d[0]), "+f"(d[1]), "+f"(d[2]), "+f"(d[3])
        : "r"(a[0]), "r"(a[1]), "r"(a[2]), "r"(a[3]), "r"(b[0]), "r"(b[1]));
}

__global__ __launch_bounds__(256, 1)
void gemm_mma_kernel(const float* __restrict__ A, const float* __restrict__ W) {
    extern __shared__ uint32_t smem[];
    uint32_t* w_hi  = smem;
    uint32_t* w_lo  = smem + W_U32;
    uint32_t* a_buf = smem + 2 * W_U32;   // [stage][term][A_U32]

    const int tid    = threadIdx.x;
    const int wid    = tid >> 5;
    const int lane   = tid & 31;
    const int warp_m = wid & 3;           // 4 row-bands of 32
    const int warp_n = wid >> 2;          // 2 col-bands of 64
    const int g      = lane >> 2;         // groupID
    const int c      = lane & 3;          // threadID_in_group

    // ---- W prologue: split fp32 W -> bf16 hi/lo directly into SMEM ----
    // thread t owns n = t&127, k parity (t>>7); halves of the same u32 are
    // written by thread pair (t, t+128) via 16-bit byte-enabled stores.
    for (int idx = tid; idx < D_IN * D_OUT; idx += 256) {
        const int n = idx & 127;          // output col (MMA B-row)
        const int k = idx >> 7;           // input dim (K)
        float w = W[(size_t)k * D_OUT + n];
        __nv_bfloat16 hb = __float2bfloat16(w);
        float hf = __bfloat162float(hb);
        __nv_bfloat16 lb = __float2bfloat16(w - hf);
        const int u = n * WSTRIDE + (k >> 1);
        const int h = k & 1;
        ((uint16_t*)&w_hi[u])[h] = *(uint16_t*)&hb;
        ((uint16_t*)&w_lo[u])[h] = *(uint16_t*)&lb;
    }
    __syncthreads();

    const int a_row  = tid >> 1;          // 0..127
    const int a_half = tid & 1;           // which 16-float half of the 32-k block

    // ---- register prefetch of the A block (software pipeline) ----
    float4 p0, p1, p2, p3;
    {
        const int gr = blockIdx.x * 128 + a_row;
        if (blockIdx.x < N_TILES && gr < N_NODES) {
            const float4* p = (const float4*)(A + (size_t)gr * D_IN + a_half * 16);
            p0 = p[0]; p1 = p[1]; p2 = p[2]; p3 = p[3];
        } else {
            p0 = p1 = p2 = p3 = make_float4(0.f, 0.f, 0.f, 0.f);
        }
    }

    for (int tile = blockIdx.x; tile < N_TILES; tile += gridDim.x) {
        const int m0 = tile * 128;

        float acc[2][8][4];
#pragma unroll
        for (int mt = 0; mt < 2; mt++)
#pragma unroll
            for (int nt = 0; nt < 8; nt++)
#pragma unroll
                for (int q = 0; q < 4; q++) acc[mt][nt][q] = 0.f;

        for (int kb = 0; kb < 8; kb++) {           // K blocks of 32
            const int stage = kb & 1;
            uint32_t* abh = a_buf + (stage * 2 + 0) * A_U32;
            uint32_t* abl = a_buf + (stage * 2 + 1) * A_U32;

            // ---- convert prefetched regs + store to smem stage ----
            {
                float f[16] = {p0.x, p0.y, p0.z, p0.w, p1.x, p1.y, p1.z, p1.w,
                               p2.x, p2.y, p2.z, p2.w, p3.x, p3.y, p3.z, p3.w};
                uint32_t hi[8], lo[8];
#pragma unroll
                for (int q = 0; q < 8; q++) {
                    uint32_t hq = pack_bf(f[2 * q], f[2 * q + 1]);
                    float h0 = __uint_as_float(hq << 16);
                    float h1 = __uint_as_float(hq & 0xFFFF0000u);
                    hi[q] = hq;
                    lo[q] = pack_bf(f[2 * q] - h0, f[2 * q + 1] - h1);
                }
                uint32_t* dh = abh + a_row * ASTRIDE + a_half * 8;
                uint32_t* dl = abl + a_row * ASTRIDE + a_half * 8;
                *(uint4*)(dh + 0) = make_uint4(hi[0], hi[1], hi[2], hi[3]);
                *(uint4*)(dh + 4) = make_uint4(hi[4], hi[5], hi[6], hi[7]);
                *(uint4*)(dl + 0) = make_uint4(lo[0], lo[1], lo[2], lo[3]);
                *(uint4*)(dl + 4) = make_uint4(lo[4], lo[5], lo[6], lo[7]);
            }

            // ---- issue prefetch for next k-block (or next tile) ----
            {
                int nkb = kb + 1, ntile = tile;
                if (nkb == 8) { nkb = 0; ntile = tile + gridDim.x; }
                const int gr = ntile * 128 + a_row;
                if (ntile < N_TILES && gr < N_NODES) {
                    const float4* p = (const float4*)(A + (size_t)gr * D_IN + nkb * 32 + a_half * 16);
                    p0 = p[0]; p1 = p[1]; p2 = p[2]; p3 = p[3];
                } else {
                    p0 = p1 = p2 = p3 = make_float4(0.f, 0.f, 0.f, 0.f);
                }
            }
            __syncthreads();

            // ---- compute: 2 k16 steps ----
#pragma unroll
            for (int kk = 0; kk < 2; kk++) {
                const int kpl = kk * 8 + c;                 // local kpair for A
                const int kpg = kb * 16 + kk * 8 + c;       // global kpair for W

                uint32_t ah[2][4], al[2][4];
#pragma unroll
                for (int mt = 0; mt < 2; mt++) {
                    const int r0 = (warp_m * 32 + mt * 16 + g) * ASTRIDE;
                    const int r1 = r0 + 8 * ASTRIDE;
                    ah[mt][0] = abh[r0 + kpl];     ah[mt][1] = abh[r1 + kpl];
                    ah[mt][2] = abh[r0 + kpl + 4]; ah[mt][3] = abh[r1 + kpl + 4];
                    al[mt][0] = abl[r0 + kpl];     al[mt][1] = abl[r1 + kpl];
                    al[mt][2] = abl[r0 + kpl + 4]; al[mt][3] = abl[r1 + kpl + 4];
                }
                uint32_t bh[8][2], bl[8][2];
#pragma unroll
                for (int nt = 0; nt < 8; nt++) {
                    const int n = warp_n * 64 + nt * 8 + g;
                    bh[nt][0] = w_hi[n * WSTRIDE + kpg];
                    bh[nt][1] = w_hi[n * WSTRIDE + kpg + 4];
                    bl[nt][0] = w_lo[n * WSTRIDE + kpg];
                    bl[nt][1] = w_lo[n * WSTRIDE + kpg + 4];
                }
#pragma unroll
                for (int mt = 0; mt < 2; mt++)
#pragma unroll
                    for (int nt = 0; nt < 8; nt++) {
                        mma16816(acc[mt][nt], ah[mt], bh[nt]);
                        mma16816(acc[mt][nt], al[mt], bh[nt]);
                        mma16816(acc[mt][nt], ah[mt], bl[nt]);
                    }
            }
        }

        // ---- epilogue: convert to fp16 (half2 per u32) ----
#pragma unroll
        for (int mt = 0; mt < 2; mt++) {
            const int r0 = m0 + warp_m * 32 + mt * 16 + g;
#pragma unroll
            for (int nt = 0; nt < 8; nt++) {
                const int u = warp_n * 32 + nt * 4 + c;     // u32 col index
                if (r0 < N_NODES) {
                    __half2 h = __floats2half2_rn(acc[mt][nt][0], acc[mt][nt][1]);
                    g_support_h[(size_t)r0 * (D_OUT / 2) + u] = *(uint32_t*)&h;
                }
                if (r0 + 8 < N_NODES) {
                    __half2 h = __floats2half2_rn(acc[mt][nt][2], acc[mt][nt][3]);
                    g_support_h[(size_t)(r0 + 8) * (D_OUT / 2) + u] = *(uint32_t*)&h;
                }
            }
        }
        __syncthreads();
    }
}

// ---------------- 2) CSR build: histogram -> scan -> scatter -------------
__global__ void hist4_kernel(const int* __restrict__ rows) {
    int t = blockIdx.x * blockDim.x + threadIdx.x;
    if (t * 4 >= N_EDGES) return;
    int4 r = ((const int4*)rows)[t];
    atomicAdd(&g_counts[r.x], 1);
    atomicAdd(&g_counts[r.y], 1);
    atomicAdd(&g_counts[r.z], 1);
    atomicAdd(&g_counts[r.w], 1);
}

__global__ __launch_bounds__(SCAN_B)
void scan1_kernel() {
    __shared__ int sh[SCAN_B];
    int i = blockIdx.x * SCAN_B + threadIdx.x;
    int v = (i < N_NODES) ? g_counts[i] : 0;
    sh[threadIdx.x] = v;
    __syncthreads();
#pragma unroll
    for (int off = 1; off < SCAN_B; off <<= 1) {
        int t = (threadIdx.x >= off) ? sh[threadIdx.x - off] : 0;
        __syncthreads();
        sh[threadIdx.x] += t;
        __syncthreads();
    }
    if (i < N_NODES) g_rowptr[i] = sh[threadIdx.x] - v;   // block-local exclusive
    if (threadIdx.x == SCAN_B - 1) g_blocksums[blockIdx.x] = sh[SCAN_B - 1];
}

// merged scan2+scan3: every block redundantly scans the 98 block sums,
// then applies its segment's exclusive prefix and seeds the cursor.
__global__ __launch_bounds__(256)
void scan23_kernel() {
    __shared__ int sh[256];
    const int t = threadIdx.x;
    const int v = (t < NSB) ? g_blocksums[t] : 0;
    sh[t] = v;
    __syncthreads();
#pragma unroll
    for (int off = 1; off < 256; off <<= 1) {
        int x = (t >= off) ? sh[t - off] : 0;
        __syncthreads();
        sh[t] += x;
        __syncthreads();
    }
    __shared__ int base;
    if (t == 0) {
        const int seg = (blockIdx.x * 256) / SCAN_B;      // constant per block
        base = sh[seg] - g_blocksums[seg];                // exclusive prefix
    }
    __syncthreads();
    const int i = blockIdx.x * 256 + t;
    if (i < N_NODES) {
        const int val = g_rowptr[i] + base;
        g_rowptr[i] = val;
        g_cursor[i] = val;
    }
    if (i == 0) g_rowptr[N_NODES] = N_EDGES;
}

__global__ void scatter4_kernel(const int* __restrict__ rows,
                                const int* __restrict__ cols,
                                const float* __restrict__ vals) {
    int t = blockIdx.x * blockDim.x + threadIdx.x;
    if (t * 4 >= N_EDGES) return;
    int4   r = ((const int4*)rows)[t];
    int4   c = ((const int4*)cols)[t];
    float4 v = ((const float4*)vals)[t];
    int p0 = atomicAdd(&g_cursor[r.x], 1);
    int p1 = atomicAdd(&g_cursor[r.y], 1);
    int p2 = atomicAdd(&g_cursor[r.z], 1);
    int p3 = atomicAdd(&g_cursor[r.w], 1);
    g_sorted_cv[p0] = make_int2(c.x, __float_as_int(v.x));
    g_sorted_cv[p1] = make_int2(c.y, __float_as_int(v.y));
    g_sorted_cv[p2] = make_int2(c.z, __float_as_int(v.z));
    g_sorted_cv[p3] = make_int2(c.w, __float_as_int(v.w));
}

// ---------------- 3) Aggregate: warp/row, shfl-broadcast edge data -------
__global__ __launch_bounds__(256)
void aggregate_kernel(const float* __restrict__ bias, float* __restrict__ out) {
    int w    = (blockIdx.x * blockDim.x + threadIdx.x) >> 5;   // row id
    int lane = threadIdx.x & 31;
    if (w >= N_NODES) return;

    const int s = g_rowptr[w];
    const int e = g_rowptr[w + 1];

    // lane covers cols lane*4 .. lane*4+3  (uint2 = 4 halves per edge)
    float4 acc = ((const float4*)bias)[lane];

    for (int base = s; base < e; base += 32) {
        const int rem = e - base;
        int2 cv = make_int2(0, 0);
        if (lane < rem) cv = g_sorted_cv[base + lane];    // one coalesced load
        const int n = rem < 32 ? rem : 32;

#pragma unroll 8
        for (int j = 0; j < n; j++) {
            const int   col = __shfl_sync(0xFFFFFFFFu, cv.x, j);
            const float v   = __int_as_float(__shfl_sync(0xFFFFFFFFu, cv.y, j));
            uint2 sv = *(const uint2*)&g_support_h[(size_t)col * 64 + lane * 2];
            float2 a = __half22float2(*(__half2*)&sv.x);
            float2 b = __half22float2(*(__half2*)&sv.y);
            acc.x += v * a.x; acc.y += v * a.y; acc.z += v * b.x; acc.w += v * b.y;
        }
    }

    *(float4*)&out[(size_t)w * D_OUT + lane * 4] = acc;
}

// ---------------- launch ------------------------------------------------
extern "C" void kernel_launch(void* const* d_in, const int* in_sizes, int n_in,
                              void* d_out, int out_size) {
    const float* in_feature = (const float*)d_in[0];   // [N, 256]
    const int*   edge_rows  = (const int*)d_in[1];     // [E]
    const int*   edge_cols  = (const int*)d_in[2];     // [E]
    const float* edge_vals  = (const float*)d_in[3];   // [E]
    const float* weight     = (const float*)d_in[4];   // [256, 128]
    const float* bias       = (const float*)d_in[5];   // [128]
    float*       out        = (float*)d_out;           // [N, 128]

    (void)in_sizes; (void)n_in; (void)out_size;

    static cudaStream_t s2 = 0;
    static cudaEvent_t ev_fork = 0, ev_join = 0;
    static void* counts_ptr = 0;
    static int init_done = 0;
    if (!init_done) {
        cudaFuncSetAttribute(gemm_mma_kernel, cudaFuncAttributeMaxDynamicSharedMemorySize, SM_TOTAL_B);
        cudaStreamCreateWithFlags(&s2, cudaStreamNonBlocking);
        cudaEventCreateWithFlags(&ev_fork, cudaEventDisableTiming);
        cudaEventCreateWithFlags(&ev_join, cudaEventDisableTiming);
        cudaGetSymbolAddress(&counts_ptr, g_counts);
        init_done = 1;
    }

    // fork: CSR build (s2) runs concurrently with GEMM (main stream)
    cudaEventRecord(ev_fork, 0);
    cudaStreamWaitEvent(s2, ev_fork, 0);

    // --- s2: CSR build front half (launch order: 1,2,3) ---
    cudaMemsetAsync(counts_ptr, 0, N_NODES * sizeof(int), s2);
    hist4_kernel<<<(N_EDGES / 4 + 255) / 256, 256, 0, s2>>>(edge_rows);
    scan1_kernel<<<NSB, SCAN_B, 0, s2>>>();
    scan23_kernel<<<(N_NODES + 255) / 256, 256, 0, s2>>>();

    // --- main stream: GEMM (4th kernel launch -> ncu capture target) ---
    gemm_mma_kernel<<<148, 256, SM_TOTAL_B>>>(in_feature, weight);

    // --- s2: CSR back half ---
    scatter4_kernel<<<(N_EDGES / 4 + 255) / 256, 256, 0, s2>>>(edge_rows, edge_cols, edge_vals);

    // join
    cudaEventRecord(ev_join, s2);
    cudaStreamWaitEvent(0, ev_join, 0);

    // 3) out = A @ support + bias   (one warp per row)
    int blocks = (N_NODES * 32 + 255) / 256;
    aggregate_kernel<<<blocks, 256>>>(bias, out);
}

// round 8
// speedup vs baseline: 1.0744x; 1.0744x over previous
#include <cuda_runtime.h>
#include <cuda_bf16.h>
#include <cuda_fp16.h>
#include <stdint.h>

#define N_NODES 100000
#define N_EDGES 1600000
#define D_IN    256
#define D_OUT   128
#define N_TILES ((N_NODES + 127) / 128)   // 782

// ---------------- device scratch (no allocations allowed) ----------------
// support stored as fp16, packed half2 in u32: [N_NODES][64] u32
__device__ uint32_t g_support_h[(size_t)N_NODES * (D_OUT / 2)];   // 25.6 MB
__device__ int   g_counts[N_NODES];
__device__ int   g_rowptr[N_NODES + 1];
__device__ int   g_cursor[N_NODES];
__device__ int2  g_sorted_cv[N_EDGES];                 // (col, val-bits) sorted by row

#define SCAN_B 1024
#define NSB    ((N_NODES + SCAN_B - 1) / SCAN_B)       // 98
__device__ int   g_blocksums[NSB];

#define WSTRIDE 132

// ---------------- 1) HMMA GEMM: support = X @ W (fp16 output) ------------
#define ASTRIDE 20
#define W_U32   (128 * WSTRIDE)
#define A_U32   (128 * ASTRIDE)
#define SM_TOTAL_B ((2 * W_U32 + 4 * A_U32) * 4)   // 176128 bytes

// pack two fp32 -> bf16x2 (f0 low half, f1 high half)
__device__ __forceinline__ uint32_t pack_bf(float f0, float f1) {
    uint32_t r;
    asm("cvt.rn.bf16x2.f32 %0, %1, %2;" : "=r"(r) : "f"(f1), "f"(f0));
    return r;
}

__device__ __forceinline__ void mma16816(float* d, const uint32_t* a, const uint32_t* b) {
    asm volatile(
        "mma.sync.aligned.m16n8k16.row.col.f32.bf16.bf16.f32 "
        "{%0,%1,%2,%3}, {%4,%5,%6,%7}, {%8,%9}, {%0,%1,%2,%3};"
        : "+f"(d[0]), "+f"(d[1]), "+f"(d[2]), "+f"(d[3])
        : "r"(a[0]), "r"(a[1]), "r"(a[2]), "r"(a[3]), "r"(b[0]), "r"(b[1]));
}

__global__ __launch_bounds__(512, 1)
void gemm_mma_kernel(const float* __restrict__ A, const float* __restrict__ W) {
    extern __shared__ uint32_t smem[];
    uint32_t* w_hi  = smem;
    uint32_t* w_lo  = smem + W_U32;
    uint32_t* a_buf = smem + 2 * W_U32;   // [stage][term][A_U32]

    const int tid    = threadIdx.x;
    const int wid    = tid >> 5;          // 0..15
    const int lane   = tid & 31;
    const int warp_m = wid & 3;           // 4 row-bands of 32
    const int warp_n = wid >> 2;          // 4 col-bands of 32
    const int g      = lane >> 2;         // groupID
    const int c      = lane & 3;          // threadID_in_group

    // ---- W prologue: split fp32 W -> bf16 hi/lo directly into SMEM ----
    for (int idx = tid; idx < D_IN * D_OUT; idx += 512) {
        const int n = idx & 127;          // output col (MMA B-row)
        const int k = idx >> 7;           // input dim (K)
        float w = W[(size_t)k * D_OUT + n];
        __nv_bfloat16 hb = __float2bfloat16(w);
        float hf = __bfloat162float(hb);
        __nv_bfloat16 lb = __float2bfloat16(w - hf);
        const int u = n * WSTRIDE + (k >> 1);
        const int h = k & 1;
        ((uint16_t*)&w_hi[u])[h] = *(uint16_t*)&hb;
        ((uint16_t*)&w_lo[u])[h] = *(uint16_t*)&lb;
    }
    __syncthreads();

    const int a_row = tid >> 2;           // 0..127
    const int a_q   = tid & 3;            // quarter: 8 floats of the 32-k block

    // ---- register prefetch of the A block (software pipeline) ----
    float4 p0, p1;
    {
        const int gr = blockIdx.x * 128 + a_row;
        if (blockIdx.x < N_TILES && gr < N_NODES) {
            const float4* p = (const float4*)(A + (size_t)gr * D_IN + a_q * 8);
            p0 = p[0]; p1 = p[1];
        } else {
            p0 = p1 = make_float4(0.f, 0.f, 0.f, 0.f);
        }
    }

    for (int tile = blockIdx.x; tile < N_TILES; tile += gridDim.x) {
        const int m0 = tile * 128;

        float acc[2][4][4];
#pragma unroll
        for (int mt = 0; mt < 2; mt++)
#pragma unroll
            for (int nt = 0; nt < 4; nt++)
#pragma unroll
                for (int q = 0; q < 4; q++) acc[mt][nt][q] = 0.f;

        for (int kb = 0; kb < 8; kb++) {           // K blocks of 32
            const int stage = kb & 1;
            uint32_t* abh = a_buf + (stage * 2 + 0) * A_U32;
            uint32_t* abl = a_buf + (stage * 2 + 1) * A_U32;

            // ---- convert prefetched regs + store to smem stage ----
            {
                float f[8] = {p0.x, p0.y, p0.z, p0.w, p1.x, p1.y, p1.z, p1.w};
                uint32_t hi[4], lo[4];
#pragma unroll
                for (int q = 0; q < 4; q++) {
                    uint32_t hq = pack_bf(f[2 * q], f[2 * q + 1]);
                    float h0 = __uint_as_float(hq << 16);
                    float h1 = __uint_as_float(hq & 0xFFFF0000u);
                    hi[q] = hq;
                    lo[q] = pack_bf(f[2 * q] - h0, f[2 * q + 1] - h1);
                }
                *(uint4*)(abh + a_row * ASTRIDE + a_q * 4) = make_uint4(hi[0], hi[1], hi[2], hi[3]);
                *(uint4*)(abl + a_row * ASTRIDE + a_q * 4) = make_uint4(lo[0], lo[1], lo[2], lo[3]);
            }

            // ---- issue prefetch for next k-block (or next tile) ----
            {
                int nkb = kb + 1, ntile = tile;
                if (nkb == 8) { nkb = 0; ntile = tile + gridDim.x; }
                const int gr = ntile * 128 + a_row;
                if (ntile < N_TILES && gr < N_NODES) {
                    const float4* p = (const float4*)(A + (size_t)gr * D_IN + nkb * 32 + a_q * 8);
                    p0 = p[0]; p1 = p[1];
                } else {
                    p0 = p1 = make_float4(0.f, 0.f, 0.f, 0.f);
                }
            }
            __syncthreads();

            // ---- compute: 2 k16 steps ----
#pragma unroll
            for (int kk = 0; kk < 2; kk++) {
                const int kpl = kk * 8 + c;                 // local kpair for A
                const int kpg = kb * 16 + kk * 8 + c;       // global kpair for W

                uint32_t ah[2][4], al[2][4];
#pragma unroll
                for (int mt = 0; mt < 2; mt++) {
                    const int r0 = (warp_m * 32 + mt * 16 + g) * ASTRIDE;
                    const int r1 = r0 + 8 * ASTRIDE;
                    ah[mt][0] = abh[r0 + kpl];     ah[mt][1] = abh[r1 + kpl];
                    ah[mt][2] = abh[r0 + kpl + 4]; ah[mt][3] = abh[r1 + kpl + 4];
                    al[mt][0] = abl[r0 + kpl];     al[mt][1] = abl[r1 + kpl];
                    al[mt][2] = abl[r0 + kpl + 4]; al[mt][3] = abl[r1 + kpl + 4];
                }
                uint32_t bh[4][2], bl[4][2];
#pragma unroll
                for (int nt = 0; nt < 4; nt++) {
                    const int n = warp_n * 32 + nt * 8 + g;
                    bh[nt][0] = w_hi[n * WSTRIDE + kpg];
                    bh[nt][1] = w_hi[n * WSTRIDE + kpg + 4];
                    bl[nt][0] = w_lo[n * WSTRIDE + kpg];
                    bl[nt][1] = w_lo[n * WSTRIDE + kpg + 4];
                }
#pragma unroll
                for (int mt = 0; mt < 2; mt++)
#pragma unroll
                    for (int nt = 0; nt < 4; nt++) {
                        mma16816(acc[mt][nt], ah[mt], bh[nt]);
                        mma16816(acc[mt][nt], al[mt], bh[nt]);
                        mma16816(acc[mt][nt], ah[mt], bl[nt]);
                    }
            }
        }

        // ---- epilogue: convert to fp16 (half2 per u32) ----
#pragma unroll
        for (int mt = 0; mt < 2; mt++) {
            const int r0 = m0 + warp_m * 32 + mt * 16 + g;
#pragma unroll
            for (int nt = 0; nt < 4; nt++) {
                const int u = warp_n * 16 + nt * 4 + c;     // u32 col index
                if (r0 < N_NODES) {
                    __half2 h = __floats2half2_rn(acc[mt][nt][0], acc[mt][nt][1]);
                    g_support_h[(size_t)r0 * (D_OUT / 2) + u] = *(uint32_t*)&h;
                }
                if (r0 + 8 < N_NODES) {
                    __half2 h = __floats2half2_rn(acc[mt][nt][2], acc[mt][nt][3]);
                    g_support_h[(size_t)(r0 + 8) * (D_OUT / 2) + u] = *(uint32_t*)&h;
                }
            }
        }
        __syncthreads();
    }
}

// ---------------- 2) CSR build: histogram -> scan -> scatter -------------
__global__ void hist4_kernel(const int* __restrict__ rows) {
    int t = blockIdx.x * blockDim.x + threadIdx.x;
    if (t * 4 >= N_EDGES) return;
    int4 r = ((const int4*)rows)[t];
    atomicAdd(&g_counts[r.x], 1);
    atomicAdd(&g_counts[r.y], 1);
    atomicAdd(&g_counts[r.z], 1);
    atomicAdd(&g_counts[r.w], 1);
}

__global__ __launch_bounds__(SCAN_B)
void scan1_kernel() {
    __shared__ int sh[SCAN_B];
    int i = blockIdx.x * SCAN_B + threadIdx.x;
    int v = (i < N_NODES) ? g_counts[i] : 0;
    sh[threadIdx.x] = v;
    __syncthreads();
#pragma unroll
    for (int off = 1; off < SCAN_B; off <<= 1) {
        int t = (threadIdx.x >= off) ? sh[threadIdx.x - off] : 0;
        __syncthreads();
        sh[threadIdx.x] += t;
        __syncthreads();
    }
    if (i < N_NODES) g_rowptr[i] = sh[threadIdx.x] - v;   // block-local exclusive
    if (threadIdx.x == SCAN_B - 1) g_blocksums[blockIdx.x] = sh[SCAN_B - 1];
}

// merged scan2+scan3: every block redundantly scans the 98 block sums,
// then applies its segment's exclusive prefix and seeds the cursor.
__global__ __launch_bounds__(256)
void scan23_kernel() {
    __shared__ int sh[256];
    const int t = threadIdx.x;
    const int v = (t < NSB) ? g_blocksums[t] : 0;
    sh[t] = v;
    __syncthreads();
#pragma unroll
    for (int off = 1; off < 256; off <<= 1) {
        int x = (t >= off) ? sh[t - off] : 0;
        __syncthreads();
        sh[t] += x;
        __syncthreads();
    }
    __shared__ int base;
    if (t == 0) {
        const int seg = (blockIdx.x * 256) / SCAN_B;      // constant per block
        base = sh[seg] - g_blocksums[seg];                // exclusive prefix
    }
    __syncthreads();
    const int i = blockIdx.x * 256 + t;
    if (i < N_NODES) {
        const int val = g_rowptr[i] + base;
        g_rowptr[i] = val;
        g_cursor[i] = val;
    }
    if (i == 0) g_rowptr[N_NODES] = N_EDGES;
}

__global__ void scatter4_kernel(const int* __restrict__ rows,
                                const int* __restrict__ cols,
                                const float* __restrict__ vals) {
    int t = blockIdx.x * blockDim.x + threadIdx.x;
    if (t * 4 >= N_EDGES) return;
    int4   r = ((const int4*)rows)[t];
    int4   c = ((const int4*)cols)[t];
    float4 v = ((const float4*)vals)[t];
    int p0 = atomicAdd(&g_cursor[r.x], 1);
    int p1 = atomicAdd(&g_cursor[r.y], 1);
    int p2 = atomicAdd(&g_cursor[r.z], 1);
    int p3 = atomicAdd(&g_cursor[r.w], 1);
    g_sorted_cv[p0] = make_int2(c.x, __float_as_int(v.x));
    g_sorted_cv[p1] = make_int2(c.y, __float_as_int(v.y));
    g_sorted_cv[p2] = make_int2(c.z, __float_as_int(v.z));
    g_sorted_cv[p3] = make_int2(c.w, __float_as_int(v.w));
}

// ---------------- 3) Aggregate: warp/row, shfl-broadcast edge data -------
__global__ __launch_bounds__(256)
void aggregate_kernel(const float* __restrict__ bias, float* __restrict__ out) {
    int w    = (blockIdx.x * blockDim.x + threadIdx.x) >> 5;   // row id
    int lane = threadIdx.x & 31;
    if (w >= N_NODES) return;

    const int s = g_rowptr[w];
    const int e = g_rowptr[w + 1];

    // lane covers cols lane*4 .. lane*4+3  (uint2 = 4 halves per edge)
    float4 acc = ((const float4*)bias)[lane];

    for (int base = s; base < e; base += 32) {
        const int rem = e - base;
        int2 cv = make_int2(0, 0);
        if (lane < rem) cv = g_sorted_cv[base + lane];    // one coalesced load
        const int n = rem < 32 ? rem : 32;

#pragma unroll 8
        for (int j = 0; j < n; j++) {
            const int   col = __shfl_sync(0xFFFFFFFFu, cv.x, j);
            const float v   = __int_as_float(__shfl_sync(0xFFFFFFFFu, cv.y, j));
            uint2 sv = *(const uint2*)&g_support_h[(size_t)col * 64 + lane * 2];
            float2 a = __half22float2(*(__half2*)&sv.x);
            float2 b = __half22float2(*(__half2*)&sv.y);
            acc.x += v * a.x; acc.y += v * a.y; acc.z += v * b.x; acc.w += v * b.y;
        }
    }

    *(float4*)&out[(size_t)w * D_OUT + lane * 4] = acc;
}

// ---------------- launch ------------------------------------------------
extern "C" void kernel_launch(void* const* d_in, const int* in_sizes, int n_in,
                              void* d_out, int out_size) {
    const float* in_feature = (const float*)d_in[0];   // [N, 256]
    const int*   edge_rows  = (const int*)d_in[1];     // [E]
    const int*   edge_cols  = (const int*)d_in[2];     // [E]
    const float* edge_vals  = (const float*)d_in[3];   // [E]
    const float* weight     = (const float*)d_in[4];   // [256, 128]
    const float* bias       = (const float*)d_in[5];   // [128]
    float*       out        = (float*)d_out;           // [N, 128]

    (void)in_sizes; (void)n_in; (void)out_size;

    static cudaStream_t s2 = 0;
    static cudaEvent_t ev_fork = 0, ev_join = 0;
    static void* counts_ptr = 0;
    static int init_done = 0;
    if (!init_done) {
        cudaFuncSetAttribute(gemm_mma_kernel, cudaFuncAttributeMaxDynamicSharedMemorySize, SM_TOTAL_B);
        cudaStreamCreateWithFlags(&s2, cudaStreamNonBlocking);
        cudaEventCreateWithFlags(&ev_fork, cudaEventDisableTiming);
        cudaEventCreateWithFlags(&ev_join, cudaEventDisableTiming);
        cudaGetSymbolAddress(&counts_ptr, g_counts);
        init_done = 1;
    }

    // fork: CSR build (s2) runs concurrently with GEMM (main stream)
    cudaEventRecord(ev_fork, 0);
    cudaStreamWaitEvent(s2, ev_fork, 0);

    // --- s2: CSR build front half (launch order: 1,2,3) ---
    cudaMemsetAsync(counts_ptr, 0, N_NODES * sizeof(int), s2);
    hist4_kernel<<<(N_EDGES / 4 + 255) / 256, 256, 0, s2>>>(edge_rows);
    scan1_kernel<<<NSB, SCAN_B, 0, s2>>>();
    scan23_kernel<<<(N_NODES + 255) / 256, 256, 0, s2>>>();

    // --- main stream: GEMM (4th kernel launch -> ncu capture target) ---
    gemm_mma_kernel<<<148, 512, SM_TOTAL_B>>>(in_feature, weight);

    // --- s2: CSR back half ---
    scatter4_kernel<<<(N_EDGES / 4 + 255) / 256, 256, 0, s2>>>(edge_rows, edge_cols, edge_vals);

    // join
    cudaEventRecord(ev_join, s2);
    cudaStreamWaitEvent(0, ev_join, 0);

    // 3) out = A @ support + bias   (one warp per row)
    int blocks = (N_NODES * 32 + 255) / 256;
    aggregate_kernel<<<blocks, 256>>>(bias, out);
}